// round 9
// baseline (speedup 1.0000x reference)
#include <cuda_runtime.h>

// Shapes (fixed by reference setup_inputs):
//   e_src: (B=16, T=1024, F=8, C=256) float32
//   d_src: (16, 128) — declared int64 but JAX x64-disabled downcasts randint
//          to int32; probe the on-disk dtype deterministically.
//   output: (Bh=8, S=128, C=256) float32
static constexpr int T  = 1024;
static constexpr int F  = 8;
static constexpr int S  = 128;
static constexpr int C  = 256;
static constexpr int C4 = C / 4;        // 64 float4 chunks per frame-feature row
static constexpr int CSPLIT = 2;        // channel halves per (b,s)
static constexpr int CH4 = C4 / CSPLIT; // 32 float4 chunks per block

__device__ __forceinline__ float4 f4add(float4 a, float4 b) {
    return make_float4(a.x + b.x, a.y + b.y, a.z + b.z, a.w + b.w);
}

// Grid (S, Bh, CSPLIT), 128 threads.
// tid%32 = c4 chunk within the half, tid/32 = fh in [0,4): thread accumulates
// features fh and fh+4 for its float4 chunk. Cross-fh combine via smem.
__global__ __launch_bounds__(128) void fs2_segment_mean_kernel(
    const float* __restrict__ e,      // (16,1024,8,256)
    const int*   __restrict__ dw,     // duration words (int32 view)
    float4* __restrict__ out4)        // (8,128,64) float4
{
    const int s   = blockIdx.x;   // 0..127
    const int b   = blockIdx.y;   // 0..7
    const int cz  = blockIdx.z;   // 0..1
    const int tid = threadIdx.x;  // 0..127
    const int c4  = tid & 31;
    const int fh  = tid >> 5;     // 0..3

    // ---- dtype probe (first 256 words; durations in [0,16)) --------------
    bool ok = true;
    #pragma unroll
    for (int k = 0; k < 2; ++k) {
        const int i = tid * 2 + k;
        const int w = dw[i];
        ok &= (i & 1) ? (w == 0) : (w >= 0 && w < 16);
    }
    const int is_i64 = __syncthreads_and(ok ? 1 : 0);

    // ---- segment start: sum of d[b, 0..s-1] ------------------------------
    __shared__ int wsum[4];
    const int base_d = b * S;
    auto loadd = [&](int j) -> int {
        return is_i64 ? dw[(base_d + j) * 2] : dw[base_d + j];
    };
    int v = (tid < s) ? loadd(tid) : 0;      // s <= 127 < 128 threads
    #pragma unroll
    for (int o = 16; o > 0; o >>= 1) v += __shfl_down_sync(0xffffffffu, v, o);
    if ((tid & 31) == 0) wsum[tid >> 5] = v;
    const int cnt = loadd(s);
    __syncthreads();

    int start = wsum[0] + wsum[1] + wsum[2] + wsum[3];
    int end = start + cnt;
    if (start > T) start = T;
    if (end   > T) end   = T;

    // ---- stream frames: 2 float4 loads (f=fh, fh+4) per t ----------------
    // Two t-accumulators -> 4 independent 16B loads in flight per thread.
    const size_t frame_stride = (size_t)F * C4;          // float4 units per t
    const float4* base = (const float4*)e
        + (size_t)b * T * frame_stride
        + (size_t)fh * C4 + cz * CH4 + c4;

    float4 acc0 = make_float4(0.f, 0.f, 0.f, 0.f);
    float4 acc1 = make_float4(0.f, 0.f, 0.f, 0.f);
    int t = start;
    for (; t + 1 < end; t += 2) {
        const float4* p0 = base + (size_t)t * frame_stride;
        const float4* p1 = p0 + frame_stride;
        float4 x0 = __ldg(p0);
        float4 y0 = __ldg(p0 + 4 * C4);
        float4 x1 = __ldg(p1);
        float4 y1 = __ldg(p1 + 4 * C4);
        acc0 = f4add(acc0, f4add(x0, y0));
        acc1 = f4add(acc1, f4add(x1, y1));
    }
    if (t < end) {
        const float4* p0 = base + (size_t)t * frame_stride;
        acc0 = f4add(acc0, f4add(__ldg(p0), __ldg(p0 + 4 * C4)));
    }
    float4 acc = f4add(acc0, acc1);

    // ---- combine the 4 fh partials per chunk, scale, store ---------------
    __shared__ float4 part[128];
    part[tid] = acc;
    __syncthreads();
    if (tid < 32) {
        float4 r = part[tid];
        r = f4add(r, part[tid + 32]);
        r = f4add(r, part[tid + 64]);
        r = f4add(r, part[tid + 96]);
        const float inv = (cnt > 0) ? (1.0f / (float)(cnt * F)) : 0.0f;
        r.x *= inv; r.y *= inv; r.z *= inv; r.w *= inv;
        out4[((size_t)b * S + s) * C4 + cz * CH4 + tid] = r;
    }
}

extern "C" void kernel_launch(void* const* d_in, const int* in_sizes, int n_in,
                              void* d_out, int out_size)
{
    const float* e = (const float*)d_in[0];  // (16,1024,8,256) fp32
    const int*   d = (const int*)d_in[1];    // durations (int32 or int64 words)
    float4*      o = (float4*)d_out;         // (8,128,256) fp32 as float4

    dim3 grid(S, /*Bh=*/8, CSPLIT);
    fs2_segment_mean_kernel<<<grid, 128>>>(e, d, o);
}